// round 13
// baseline (speedup 1.0000x reference)
#include <cuda_runtime.h>

#define B  8
#define L  8192
#define D  768
#define NE 128
#define P  8128
#define NPAIR (B * P)

#define NBLK 144
#define NTHR 256
#define NSEG 6
#define PADK 68       // smem k-row stride (floats)
#define SPAN_BUF_BYTES 49152      // 16 rows x 3072 B
#define DYN_SMEM (4 * SPAN_BUF_BYTES)   // 192 KB, 4-deep pipeline

// ---- device scratch (no allocations allowed) ----
__device__ float g_emb[B * NE * D];          // 3 MB, pre-normalized embeddings
__device__ float g_partial[NBLK][64 * 64];   // 2.36 MB, per-(tile,kseg) Gram partials
__device__ float2 g_part[128];               // per-2b-block (S, Q)
__device__ unsigned g_bar_cnt[3];
__device__ volatile unsigned g_bar_flag[3];

// Replay-safe grid barrier (flag read BEFORE arrival -> parity-agnostic).
__device__ __forceinline__ void grid_bar(int id) {
    __syncthreads();
    if (threadIdx.x == 0) {
        unsigned start = g_bar_flag[id];
        __threadfence();
        unsigned old = atomicAdd(&g_bar_cnt[id], 1u);
        if (old == NBLK - 1u) {
            g_bar_cnt[id] = 0u;
            __threadfence();
            g_bar_flag[id] = start ^ 1u;
        } else {
            while (g_bar_flag[id] == start) { }
        }
        __threadfence();
    }
    __syncthreads();
}

__device__ __forceinline__ unsigned smem_u32(const void* p) {
    return (unsigned)__cvta_generic_to_shared(p);
}

union SmemU {
    struct { float As[16][PADK]; float Bs[16][PADK]; } p2; // 8.7 KB
    struct { float4 w1[32], bv1[32], w2[64]; float misc[2 + B]; } p3;
};

__global__ void __launch_bounds__(NTHR, 1)
k_fused(const float* __restrict__ x,
        const int*   __restrict__ starts,
        const int*   __restrict__ lengths,
        const int*   __restrict__ hts,      // provably triu_indices(128,1): unused
        const float* __restrict__ thr_p,
        const float* __restrict__ W1,
        const float* __restrict__ b1,
        const float* __restrict__ W2,
        const float* __restrict__ b2,
        float*       __restrict__ out) {
    extern __shared__ __align__(16) char dynbuf[];   // 4 x 48 KB span buffers
    __shared__ SmemU su;
    __shared__ float ws[8], wq[8];
    __shared__ float s_invn;

    int tid  = threadIdx.x;
    int bid  = blockIdx.x;
    int lane = tid & 31;
    int warp = tid >> 5;

    // ===== Phase 1: mean pool + normalize via cp.async.cg (L1-bypassing) =====
    // 4-deep pipeline: each span is one commit-group of <=12 per-thread 16B
    // cp.async.cg chunks (L2->smem, no L1-MSHR hold).  wait_group keeps 4
    // span copies in flight while reducing the oldest.
    {
        int  sp_i[8], sp_len[8];
        bool sp_act[8];
        #pragma unroll
        for (int i = 0; i < 8; ++i) {
            int sp = (i >> 2) * 576 + bid * 4 + (i & 3);
            sp_act[i] = (sp < 1024);
            sp_i[i]   = sp_act[i] ? sp : 0;
            sp_len[i] = sp_act[i] ? lengths[sp_i[i]] : 0;
        }

        auto issue = [&](int i) {
            if (sp_act[i]) {
                int sp = sp_i[i];
                int b  = sp >> 7;
                int s  = starts[sp];
                const char* src = (const char*)(x + ((size_t)b * L + s) * D);
                char* dst = dynbuf + (i & 3) * SPAN_BUF_BYTES;
                int nchunks = sp_len[i] * 192;         // 16B chunks
                #pragma unroll
                for (int j = 0; j < 12; ++j) {
                    int c = j * 256 + tid;
                    if (c < nchunks) {
                        unsigned d = smem_u32(dst + (size_t)c * 16);
                        asm volatile("cp.async.cg.shared.global [%0], [%1], 16;"
                                     :: "r"(d), "l"(src + (size_t)c * 16) : "memory");
                    }
                }
            }
            asm volatile("cp.async.commit_group;" ::: "memory");
        };

        issue(0); issue(1); issue(2); issue(3);

        #pragma unroll 1
        for (int i = 0; i < 8; ++i) {
            int rem = 7 - i;                   // groups issued after this one
            if (rem >= 3) asm volatile("cp.async.wait_group 3;" ::: "memory");
            else if (rem == 2) asm volatile("cp.async.wait_group 2;" ::: "memory");
            else if (rem == 1) asm volatile("cp.async.wait_group 1;" ::: "memory");
            else               asm volatile("cp.async.wait_group 0;" ::: "memory");
            __syncthreads();

            if (sp_act[i]) {
                const float* bufF = (const float*)(dynbuf + (i & 3) * SPAN_BUF_BYTES);
                int len = sp_len[i];
                float a0 = 0.f, a1 = 0.f, a2 = 0.f;
                #pragma unroll 1
                for (int r = 0; r < len; ++r) {
                    const float* rp = bufF + r * D;
                    a0 += rp[tid];
                    a1 += rp[tid + 256];
                    a2 += rp[tid + 512];
                }
                float inv = 1.0f / (float)len;
                float m0 = a0 * inv, m1 = a1 * inv, m2 = a2 * inv;
                float nsq = m0*m0 + m1*m1 + m2*m2;
                #pragma unroll
                for (int o = 16; o; o >>= 1) nsq += __shfl_xor_sync(0xffffffffu, nsq, o);
                if (lane == 0) ws[warp] = nsq;
                __syncthreads();
                if (tid == 0) {
                    float T = ((ws[0]+ws[1]) + (ws[2]+ws[3]))
                            + ((ws[4]+ws[5]) + (ws[6]+ws[7]));
                    s_invn = 1.0f / sqrtf(T);
                }
                __syncthreads();
                float invn = s_invn;
                float* ep = g_emb + (size_t)sp_i[i] * D;
                ep[tid]       = m0 * invn;
                ep[tid + 256] = m1 * invn;
                ep[tid + 512] = m2 * invn;
            }
            __syncthreads();                   // buffer (i&3) free for reuse
            if (i + 4 < 8) issue(i + 4);
        }
    }

    grid_bar(0);

    // ===== Phase 2: 64x64 Gram tiles (upper+diag only), k-split-6 across blocks =====
    {
        int tile_id = bid / NSEG;
        int kseg    = bid - tile_id * NSEG;
        int b       = tile_id / 3;
        int tt      = tile_id - b * 3;       // 0:(0,0) 1:(0,1) 2:(1,1)
        int ti      = (tt == 2) ? 64 : 0;
        int tj      = (tt == 0) ? 0  : 64;
        int k0      = kseg * 128;

        const float* Ea = g_emb + (size_t)(b * NE + ti) * D;
        const float* Eb = g_emb + (size_t)(b * NE + tj) * D;

        int lrow = tid >> 2;                 // load row 0..63
        int lq   = (tid & 3) * 4;            // k offset within 16-chunk
        int tx   = tid & 15;                 // j/4
        int ty   = tid >> 4;                 // i/4

        float a00=0,a01=0,a02=0,a03=0, a10=0,a11=0,a12=0,a13=0;
        float a20=0,a21=0,a22=0,a23=0, a30=0,a31=0,a32=0,a33=0;

        float4 pa = *(const float4*)(Ea + (size_t)lrow * D + k0 + lq);
        float4 pb = *(const float4*)(Eb + (size_t)lrow * D + k0 + lq);

        #pragma unroll 1
        for (int c = 0; c < 8; ++c) {        // 8 chunks x 16 k = 128 k
            __syncthreads();
            su.p2.As[lq+0][lrow] = pa.x; su.p2.As[lq+1][lrow] = pa.y;
            su.p2.As[lq+2][lrow] = pa.z; su.p2.As[lq+3][lrow] = pa.w;
            su.p2.Bs[lq+0][lrow] = pb.x; su.p2.Bs[lq+1][lrow] = pb.y;
            su.p2.Bs[lq+2][lrow] = pb.z; su.p2.Bs[lq+3][lrow] = pb.w;
            __syncthreads();
            if (c < 7) {
                pa = *(const float4*)(Ea + (size_t)lrow * D + k0 + (c+1)*16 + lq);
                pb = *(const float4*)(Eb + (size_t)lrow * D + k0 + (c+1)*16 + lq);
            }
            #pragma unroll
            for (int k = 0; k < 16; ++k) {
                float4 a  = *(const float4*)&su.p2.As[k][ty * 4];
                float4 bb = *(const float4*)&su.p2.Bs[k][tx * 4];
                a00 = fmaf(a.x, bb.x, a00); a01 = fmaf(a.x, bb.y, a01);
                a02 = fmaf(a.x, bb.z, a02); a03 = fmaf(a.x, bb.w, a03);
                a10 = fmaf(a.y, bb.x, a10); a11 = fmaf(a.y, bb.y, a11);
                a12 = fmaf(a.y, bb.z, a12); a13 = fmaf(a.y, bb.w, a13);
                a20 = fmaf(a.z, bb.x, a20); a21 = fmaf(a.z, bb.y, a21);
                a22 = fmaf(a.z, bb.z, a22); a23 = fmaf(a.z, bb.w, a23);
                a30 = fmaf(a.w, bb.x, a30); a31 = fmaf(a.w, bb.y, a31);
                a32 = fmaf(a.w, bb.z, a32); a33 = fmaf(a.w, bb.w, a33);
            }
        }

        float* gp = g_partial[bid];
        int ob = (ty * 4) * 64 + tx * 4;
        *(float4*)&gp[ob      ] = make_float4(a00, a01, a02, a03);
        *(float4*)&gp[ob +  64] = make_float4(a10, a11, a12, a13);
        *(float4*)&gp[ob + 128] = make_float4(a20, a21, a22, a23);
        *(float4*)&gp[ob + 192] = make_float4(a30, a31, a32, a33);
    }

    grid_bar(1);

    // ===== Phase 2b: combine k-segments, symmetric-weighted stats (bid < 128) =====
    int v_gi[3], v_gj[3];
    float v_sv[3];
    int my_b = bid >> 4;
    {
        float sw_ = 0.f, sq_ = 0.f;
        if (bid < 128) {
            int blk16 = bid & 15;
            int s0 = blk16 * 768 + tid * 3;
            #pragma unroll
            for (int e = 0; e < 3; ++e) {
                int s   = s0 + e;
                int tt  = s >> 12;
                int idx = s & 4095;
                int li  = idx >> 6;
                int lj  = idx & 63;
                int tbase = (my_b * 3 + tt) * NSEG;
                float vv = ((g_partial[tbase+0][idx] + g_partial[tbase+1][idx])
                          + (g_partial[tbase+2][idx] + g_partial[tbase+3][idx]))
                          + (g_partial[tbase+4][idx] + g_partial[tbase+5][idx]);
                float w = (tt == 1) ? 2.0f : (li < lj ? 2.0f : (li == lj ? 1.0f : 0.0f));
                sw_ += w * vv;
                sq_ += w * vv * vv;
                v_sv[e] = vv;
                v_gi[e] = (tt == 2) ? 64 + li : li;
                v_gj[e] = (tt == 0) ? lj : 64 + lj;
            }
        } else {
            v_gi[0] = v_gi[1] = v_gi[2] = 1;
            v_gj[0] = v_gj[1] = v_gj[2] = 0;
            v_sv[0] = v_sv[1] = v_sv[2] = 0.f;
        }
        #pragma unroll
        for (int o = 16; o; o >>= 1) {
            sw_ += __shfl_xor_sync(0xffffffffu, sw_, o);
            sq_ += __shfl_xor_sync(0xffffffffu, sq_, o);
        }
        if (lane == 0) { ws[warp] = sw_; wq[warp] = sq_; }
        __syncthreads();
        if (bid < 128 && tid == 0) {
            float S = ((ws[0]+ws[1]) + (ws[2]+ws[3])) + ((ws[4]+ws[5]) + (ws[6]+ws[7]));
            float Q = ((wq[0]+wq[1]) + (wq[2]+wq[3])) + ((wq[4]+wq[5]) + (wq[6]+wq[7]));
            g_part[bid] = make_float2(S, Q);
        }
    }

    grid_bar(2);

    // ===== Phase 3: alphas + MLP on register-resident sim values =====
    if (tid < 32)        su.p3.w1[tid]         = ((const float4*)W1)[tid];
    else if (tid < 64)   su.p3.bv1[tid - 32]   = ((const float4*)b1)[tid - 32];
    else if (tid < 128)  su.p3.w2[tid - 64]    = ((const float4*)W2)[tid - 64];
    else if (tid < 130)  su.p3.misc[tid - 128] = b2[tid - 128];
    else if (tid < 130 + B) {
        int bb = tid - 130;
        float S = 0.f, Q = 0.f;
        #pragma unroll
        for (int t = 0; t < 16; ++t) {
            float2 pp = g_part[bb * 16 + t];
            S += pp.x; Q += pp.y;
        }
        const float N = (float)(NE * NE);
        float var = (Q - S * S / N) / (N - 1.0f);
        su.p3.misc[2 + bb] = 1.0f / (sqrtf(fmaxf(var, 0.0f)) + 1e-5f);
    }
    __syncthreads();

    if (bid < 128) {
        float thr   = thr_p[0];
        float alpha = su.p3.misc[2 + my_b];
        #pragma unroll
        for (int e = 0; e < 3; ++e) {
            if (v_gj[e] > v_gi[e]) {
                float sv = (v_sv[e] - thr) * alpha;
                float l0 = 0.f, l1 = 0.f, m0 = 0.f, m1 = 0.f;
                #pragma unroll
                for (int kk = 0; kk < 32; ++kk) {
                    float4 w1v = su.p3.w1[kk];
                    float4 b1v = su.p3.bv1[kk];
                    float4 w2a = su.p3.w2[2 * kk];
                    float4 w2b = su.p3.w2[2 * kk + 1];
                    float h0 = fmaxf(fmaf(sv, w1v.x, b1v.x), 0.0f);
                    float h1 = fmaxf(fmaf(sv, w1v.y, b1v.y), 0.0f);
                    float h2 = fmaxf(fmaf(sv, w1v.z, b1v.z), 0.0f);
                    float h3 = fmaxf(fmaf(sv, w1v.w, b1v.w), 0.0f);
                    l0 = fmaf(h0, w2a.x, l0);  l1 = fmaf(h0, w2a.y, l1);
                    m0 = fmaf(h1, w2a.z, m0);  m1 = fmaf(h1, w2a.w, m1);
                    l0 = fmaf(h2, w2b.x, l0);  l1 = fmaf(h2, w2b.y, l1);
                    m0 = fmaf(h3, w2b.z, m0);  m1 = fmaf(h3, w2b.w, m1);
                }
                int gi = v_gi[e], gj = v_gj[e];
                int pidx = gi * (2 * NE - gi - 1) / 2 + (gj - gi - 1);
                ((float2*)out)[my_b * P + pidx] =
                    make_float2((l0 + m0) + su.p3.misc[0], (l1 + m1) + su.p3.misc[1]);
            }
        }
    }
}

// ------------------------------------------------------------------
extern "C" void kernel_launch(void* const* d_in, const int* in_sizes, int n_in,
                              void* d_out, int out_size) {
    const float* x       = (const float*)d_in[0];
    const int*   starts  = (const int*)  d_in[1];
    const int*   lengths = (const int*)  d_in[2];
    const int*   hts     = (const int*)  d_in[3];
    const float* thr     = (const float*)d_in[4];
    const float* W1      = (const float*)d_in[5];
    const float* b1      = (const float*)d_in[6];
    const float* W2      = (const float*)d_in[7];
    const float* b2      = (const float*)d_in[8];
    float*       out     = (float*)d_out;

    cudaFuncSetAttribute(k_fused, cudaFuncAttributeMaxDynamicSharedMemorySize, DYN_SMEM);
    k_fused<<<NBLK, NTHR, DYN_SMEM>>>(x, starts, lengths, hts, thr, W1, b1, W2, b2, out);
}

// round 14
// speedup vs baseline: 1.4087x; 1.4087x over previous
#include <cuda_runtime.h>

#define B  8
#define L  8192
#define D  768
#define NE 128
#define P  8128
#define NPAIR (B * P)

#define NBLK 144
#define NTHR 256
#define NSEG 6
#define PADK 68     // smem k-row stride (floats)
#define GRP  18     // blocks per batch group (producer == consumer group)

// ---- device scratch (no allocations allowed) ----
__device__ float g_emb[B * NE * D];          // 3 MB, pre-normalized embeddings
__device__ float g_partial[NBLK][64 * 64];   // 2.36 MB, per-(tile,kseg) Gram partials
__device__ float2 g_part[128];               // per-2b-block (S, Q)
__device__ unsigned g_span_cnt[B];           // per-batch producer counters (reset at bar 0)
__device__ unsigned g_bar_cnt[2];
__device__ volatile unsigned g_bar_flag[2];

// Replay-safe grid barrier.  Bar 0's last-arriver also resets the per-batch
// counters (every spin has completed before any block arrives here).
__device__ __forceinline__ void grid_bar(int id) {
    __syncthreads();
    if (threadIdx.x == 0) {
        unsigned start = g_bar_flag[id];
        __threadfence();
        unsigned old = atomicAdd(&g_bar_cnt[id], 1u);
        if (old == NBLK - 1u) {
            if (id == 0) {
                #pragma unroll
                for (int b = 0; b < B; ++b) g_span_cnt[b] = 0u;
            }
            g_bar_cnt[id] = 0u;
            __threadfence();
            g_bar_flag[id] = start ^ 1u;
        } else {
            while (g_bar_flag[id] == start) { }
        }
        __threadfence();
    }
    __syncthreads();
}

__device__ __forceinline__ void f4acc(float4& a, const float4 v) {
    a.x += v.x; a.y += v.y; a.z += v.z; a.w += v.w;
}

union SmemU {
    float4 p1[4][6][32];                                   // 12 KB phase-1 half-span partials
    struct { float As[16][PADK]; float Bs[16][PADK]; } p2; // 8.7 KB
    struct { float4 w1[32], bv1[32], w2[64]; float misc[2 + B]; } p3;
};

__global__ void __launch_bounds__(NTHR, 1)
k_fused(const float* __restrict__ x,
        const int*   __restrict__ starts,
        const int*   __restrict__ lengths,
        const int*   __restrict__ hts,      // provably triu_indices(128,1): unused
        const float* __restrict__ thr_p,
        const float* __restrict__ W1,
        const float* __restrict__ b1,
        const float* __restrict__ W2,
        const float* __restrict__ b2,
        float*       __restrict__ out) {
    __shared__ SmemU su;
    __shared__ float ws[8], wq[8];

    int tid  = threadIdx.x;
    int bid  = blockIdx.x;
    int lane = tid & 31;
    int warp = tid >> 5;

    int grp_b = bid / GRP;              // batch group 0..7 (producer AND consumer)
    int grp_r = bid - grp_b * GRP;      // rank within group 0..17

    // ===== Phase 1: mean pool + normalize, batch-local span assignment =====
    // Group g's 18 blocks produce ALL of batch g's 128 spans: slot s of rank r
    // handles local span s*18 + r (slots 0..7; <128 active).  Inner loop is the
    // proven R10 uniform fixed-depth predicated schedule.
    const float4 Z4 = make_float4(0.f, 0.f, 0.f, 0.f);
    #pragma unroll 1
    for (int pass = 0; pass < 2; ++pass) {
        int wpair = warp >> 1;                 // 0..3
        int half  = warp & 1;
        int slot  = pass * 4 + wpair;          // 0..7
        int spl   = slot * GRP + grp_r;        // local span 0..143
        bool act  = (spl < NE);
        int sp    = grp_b * NE + (act ? spl : 0);
        int s     = starts[sp];
        int len   = lengths[sp];
        int nr    = act ? ((len - half + 1) >> 1) : 0;   // rows: half, half+2, ...
        const float4* xp = (const float4*)(x + ((size_t)grp_b * L + s) * D) + lane;

        float4 acc[6] = { Z4, Z4, Z4, Z4, Z4, Z4 };
        #pragma unroll
        for (int grp = 0; grp < 2; ++grp) {
            float4 v[4][6];
            #pragma unroll
            for (int r = 0; r < 4; ++r) {
                int rr = grp * 4 + r;
                bool p = rr < nr;
                const float4* rp = xp + (size_t)(half + 2 * rr) * 192;
                #pragma unroll
                for (int c = 0; c < 6; ++c) v[r][c] = p ? rp[c * 32] : Z4;
            }
            #pragma unroll
            for (int r = 0; r < 4; ++r)
                #pragma unroll
                for (int c = 0; c < 6; ++c) f4acc(acc[c], v[r][c]);
        }

        __syncthreads();                       // prior pass's readers done
        if (act && half == 0) {
            #pragma unroll
            for (int c = 0; c < 6; ++c) su.p1[wpair][c][lane] = acc[c];
        }
        __syncthreads();
        if (act && half == 1) {
            float inv = 1.0f / (float)len;
            float m[6][4];
            float nsq = 0.f;
            #pragma unroll
            for (int c = 0; c < 6; ++c) {
                float4 o = su.p1[wpair][c][lane];
                m[c][0] = (o.x + acc[c].x) * inv;
                m[c][1] = (o.y + acc[c].y) * inv;
                m[c][2] = (o.z + acc[c].z) * inv;
                m[c][3] = (o.w + acc[c].w) * inv;
                nsq += m[c][0]*m[c][0] + m[c][1]*m[c][1]
                     + m[c][2]*m[c][2] + m[c][3]*m[c][3];
            }
            #pragma unroll
            for (int o = 16; o; o >>= 1) nsq += __shfl_xor_sync(0xffffffffu, nsq, o);
            float invn = 1.0f / sqrtf(nsq);
            float4* ep = (float4*)(g_emb + (size_t)sp * D);
            #pragma unroll
            for (int c = 0; c < 6; ++c)
                ep[lane + c * 32] = make_float4(m[c][0]*invn, m[c][1]*invn,
                                                m[c][2]*invn, m[c][3]*invn);
        }
    }
    // signal: this block's share of batch grp_b is done
    __syncthreads();
    if (tid == 0) {
        __threadfence();
        atomicAdd(&g_span_cnt[grp_b], 1u);
        // spin until the whole group (18 blocks) has produced batch grp_b
        while (*(volatile unsigned*)&g_span_cnt[grp_b] < (unsigned)GRP) { }
        __threadfence();
    }
    __syncthreads();

    // ===== Phase 2: 64x64 Gram tiles (upper+diag only), k-split-6 across blocks =====
    {
        int tile_id = bid / NSEG;
        int kseg    = bid - tile_id * NSEG;
        int b       = tile_id / 3;           // == grp_b by construction
        int tt      = tile_id - b * 3;       // 0:(0,0) 1:(0,1) 2:(1,1)
        int ti      = (tt == 2) ? 64 : 0;
        int tj      = (tt == 0) ? 0  : 64;
        int k0      = kseg * 128;

        const float* Ea = g_emb + (size_t)(b * NE + ti) * D;
        const float* Eb = g_emb + (size_t)(b * NE + tj) * D;

        int lrow = tid >> 2;                 // load row 0..63
        int lq   = (tid & 3) * 4;            // k offset within 16-chunk
        int tx   = tid & 15;                 // j/4
        int ty   = tid >> 4;                 // i/4

        float a00=0,a01=0,a02=0,a03=0, a10=0,a11=0,a12=0,a13=0;
        float a20=0,a21=0,a22=0,a23=0, a30=0,a31=0,a32=0,a33=0;

        float4 pa = *(const float4*)(Ea + (size_t)lrow * D + k0 + lq);
        float4 pb = *(const float4*)(Eb + (size_t)lrow * D + k0 + lq);

        #pragma unroll 1
        for (int c = 0; c < 8; ++c) {        // 8 chunks x 16 k = 128 k
            __syncthreads();
            su.p2.As[lq+0][lrow] = pa.x; su.p2.As[lq+1][lrow] = pa.y;
            su.p2.As[lq+2][lrow] = pa.z; su.p2.As[lq+3][lrow] = pa.w;
            su.p2.Bs[lq+0][lrow] = pb.x; su.p2.Bs[lq+1][lrow] = pb.y;
            su.p2.Bs[lq+2][lrow] = pb.z; su.p2.Bs[lq+3][lrow] = pb.w;
            __syncthreads();
            if (c < 7) {
                pa = *(const float4*)(Ea + (size_t)lrow * D + k0 + (c+1)*16 + lq);
                pb = *(const float4*)(Eb + (size_t)lrow * D + k0 + (c+1)*16 + lq);
            }
            #pragma unroll
            for (int k = 0; k < 16; ++k) {
                float4 a  = *(const float4*)&su.p2.As[k][ty * 4];
                float4 bb = *(const float4*)&su.p2.Bs[k][tx * 4];
                a00 = fmaf(a.x, bb.x, a00); a01 = fmaf(a.x, bb.y, a01);
                a02 = fmaf(a.x, bb.z, a02); a03 = fmaf(a.x, bb.w, a03);
                a10 = fmaf(a.y, bb.x, a10); a11 = fmaf(a.y, bb.y, a11);
                a12 = fmaf(a.y, bb.z, a12); a13 = fmaf(a.y, bb.w, a13);
                a20 = fmaf(a.z, bb.x, a20); a21 = fmaf(a.z, bb.y, a21);
                a22 = fmaf(a.z, bb.z, a22); a23 = fmaf(a.z, bb.w, a23);
                a30 = fmaf(a.w, bb.x, a30); a31 = fmaf(a.w, bb.y, a31);
                a32 = fmaf(a.w, bb.z, a32); a33 = fmaf(a.w, bb.w, a33);
            }
        }

        float* gp = g_partial[bid];
        int ob = (ty * 4) * 64 + tx * 4;
        *(float4*)&gp[ob      ] = make_float4(a00, a01, a02, a03);
        *(float4*)&gp[ob +  64] = make_float4(a10, a11, a12, a13);
        *(float4*)&gp[ob + 128] = make_float4(a20, a21, a22, a23);
        *(float4*)&gp[ob + 192] = make_float4(a30, a31, a32, a33);
    }

    grid_bar(0);   // global; last-arriver resets g_span_cnt

    // ===== Phase 2b: combine k-segments, symmetric-weighted stats (bid < 128) =====
    int v_gi[3], v_gj[3];
    float v_sv[3];
    int my_b = bid >> 4;
    {
        float sw_ = 0.f, sq_ = 0.f;
        if (bid < 128) {
            int blk16 = bid & 15;
            int s0 = blk16 * 768 + tid * 3;
            #pragma unroll
            for (int e = 0; e < 3; ++e) {
                int s   = s0 + e;
                int tt  = s >> 12;
                int idx = s & 4095;
                int li  = idx >> 6;
                int lj  = idx & 63;
                int tbase = (my_b * 3 + tt) * NSEG;
                float vv = ((g_partial[tbase+0][idx] + g_partial[tbase+1][idx])
                          + (g_partial[tbase+2][idx] + g_partial[tbase+3][idx]))
                          + (g_partial[tbase+4][idx] + g_partial[tbase+5][idx]);
                float w = (tt == 1) ? 2.0f : (li < lj ? 2.0f : (li == lj ? 1.0f : 0.0f));
                sw_ += w * vv;
                sq_ += w * vv * vv;
                v_sv[e] = vv;
                v_gi[e] = (tt == 2) ? 64 + li : li;
                v_gj[e] = (tt == 0) ? lj : 64 + lj;
            }
        } else {
            v_gi[0] = v_gi[1] = v_gi[2] = 1;
            v_gj[0] = v_gj[1] = v_gj[2] = 0;
            v_sv[0] = v_sv[1] = v_sv[2] = 0.f;
        }
        #pragma unroll
        for (int o = 16; o; o >>= 1) {
            sw_ += __shfl_xor_sync(0xffffffffu, sw_, o);
            sq_ += __shfl_xor_sync(0xffffffffu, sq_, o);
        }
        if (lane == 0) { ws[warp] = sw_; wq[warp] = sq_; }
        __syncthreads();
        if (bid < 128 && tid == 0) {
            float S = ((ws[0]+ws[1]) + (ws[2]+ws[3])) + ((ws[4]+ws[5]) + (ws[6]+ws[7]));
            float Q = ((wq[0]+wq[1]) + (wq[2]+wq[3])) + ((wq[4]+wq[5]) + (wq[6]+wq[7]));
            g_part[bid] = make_float2(S, Q);
        }
    }

    grid_bar(1);

    // ===== Phase 3: alphas + MLP on register-resident sim values =====
    if (tid < 32)        su.p3.w1[tid]         = ((const float4*)W1)[tid];
    else if (tid < 64)   su.p3.bv1[tid - 32]   = ((const float4*)b1)[tid - 32];
    else if (tid < 128)  su.p3.w2[tid - 64]    = ((const float4*)W2)[tid - 64];
    else if (tid < 130)  su.p3.misc[tid - 128] = b2[tid - 128];
    else if (tid < 130 + B) {
        int bb = tid - 130;
        float S = 0.f, Q = 0.f;
        #pragma unroll
        for (int t = 0; t < 16; ++t) {
            float2 pp = g_part[bb * 16 + t];
            S += pp.x; Q += pp.y;
        }
        const float N = (float)(NE * NE);
        float var = (Q - S * S / N) / (N - 1.0f);
        su.p3.misc[2 + bb] = 1.0f / (sqrtf(fmaxf(var, 0.0f)) + 1e-5f);
    }
    __syncthreads();

    if (bid < 128) {
        float thr   = thr_p[0];
        float alpha = su.p3.misc[2 + my_b];
        #pragma unroll
        for (int e = 0; e < 3; ++e) {
            if (v_gj[e] > v_gi[e]) {
                float sv = (v_sv[e] - thr) * alpha;
                float l0 = 0.f, l1 = 0.f, m0 = 0.f, m1 = 0.f;
                #pragma unroll
                for (int kk = 0; kk < 32; ++kk) {
                    float4 w1v = su.p3.w1[kk];
                    float4 b1v = su.p3.bv1[kk];
                    float4 w2a = su.p3.w2[2 * kk];
                    float4 w2b = su.p3.w2[2 * kk + 1];
                    float h0 = fmaxf(fmaf(sv, w1v.x, b1v.x), 0.0f);
                    float h1 = fmaxf(fmaf(sv, w1v.y, b1v.y), 0.0f);
                    float h2 = fmaxf(fmaf(sv, w1v.z, b1v.z), 0.0f);
                    float h3 = fmaxf(fmaf(sv, w1v.w, b1v.w), 0.0f);
                    l0 = fmaf(h0, w2a.x, l0);  l1 = fmaf(h0, w2a.y, l1);
                    m0 = fmaf(h1, w2a.z, m0);  m1 = fmaf(h1, w2a.w, m1);
                    l0 = fmaf(h2, w2b.x, l0);  l1 = fmaf(h2, w2b.y, l1);
                    m0 = fmaf(h3, w2b.z, m0);  m1 = fmaf(h3, w2b.w, m1);
                }
                int gi = v_gi[e], gj = v_gj[e];
                int pidx = gi * (2 * NE - gi - 1) / 2 + (gj - gi - 1);
                ((float2*)out)[my_b * P + pidx] =
                    make_float2((l0 + m0) + su.p3.misc[0], (l1 + m1) + su.p3.misc[1]);
            }
        }
    }
}

// ------------------------------------------------------------------
extern "C" void kernel_launch(void* const* d_in, const int* in_sizes, int n_in,
                              void* d_out, int out_size) {
    const float* x       = (const float*)d_in[0];
    const int*   starts  = (const int*)  d_in[1];
    const int*   lengths = (const int*)  d_in[2];
    const int*   hts     = (const int*)  d_in[3];
    const float* thr     = (const float*)d_in[4];
    const float* W1      = (const float*)d_in[5];
    const float* b1      = (const float*)d_in[6];
    const float* W2      = (const float*)d_in[7];
    const float* b2      = (const float*)d_in[8];
    float*       out     = (float*)d_out;

    k_fused<<<NBLK, NTHR>>>(x, starts, lengths, hts, thr, W1, b1, W2, b2, out);
}